// round 4
// baseline (speedup 1.0000x reference)
#include <cuda_runtime.h>
#include <cuda_fp16.h>
#include <math.h>

#define NB 16
#define NV 256
#define NR 1024
#define RMASK 1023
#define VMASK 255
#define CS 1056          // smem column stride (1024 + 32 wrap extension), even -> 8B-aligned pairs

// OS-CFAR intermediate: half2 packs two adjacent v-rows; values pre-scaled by alpha/16. 8.4 MB.
__device__ __half2 g_os2[(NB * NV / 2) * NR];

#define CAS2(a, b) do { __half2 _hi = __hmax2(a, b); __half2 _lo = __hmin2(a, b); (a) = _hi; (b) = _lo; } while (0)

// Batcher odd-even mergesort, 8 elems, descending (19 comparators).
__device__ __forceinline__ void sort8h(__half2* x) {
    CAS2(x[0], x[1]); CAS2(x[2], x[3]); CAS2(x[0], x[2]); CAS2(x[1], x[3]); CAS2(x[1], x[2]);
    CAS2(x[4], x[5]); CAS2(x[6], x[7]); CAS2(x[4], x[6]); CAS2(x[5], x[7]); CAS2(x[5], x[6]);
    CAS2(x[0], x[4]); CAS2(x[2], x[6]); CAS2(x[2], x[4]);
    CAS2(x[1], x[5]); CAS2(x[3], x[7]); CAS2(x[3], x[5]);
    CAS2(x[1], x[2]); CAS2(x[3], x[4]); CAS2(x[5], x[6]);
}

// M = sorted-desc top-8 of (sorted a) U (sorted b): half-cleaner + bitonic sort-8.
__device__ __forceinline__ void merge_top8(const __half2* a, const __half2* b, __half2* m) {
    m[0] = __hmax2(a[0], b[7]); m[1] = __hmax2(a[1], b[6]);
    m[2] = __hmax2(a[2], b[5]); m[3] = __hmax2(a[3], b[4]);
    m[4] = __hmax2(a[4], b[3]); m[5] = __hmax2(a[5], b[2]);
    m[6] = __hmax2(a[6], b[1]); m[7] = __hmax2(a[7], b[0]);
    CAS2(m[0], m[4]); CAS2(m[1], m[5]); CAS2(m[2], m[6]); CAS2(m[3], m[7]);
    CAS2(m[0], m[2]); CAS2(m[1], m[3]); CAS2(m[4], m[6]); CAS2(m[5], m[7]);
    CAS2(m[0], m[1]); CAS2(m[2], m[3]); CAS2(m[4], m[5]); CAS2(m[6], m[7]);
}

// 8th largest of union of two sorted-desc-8 lists = min_i max(A[i], B[7-i]).
__device__ __forceinline__ __half2 kth8(const __half2* a, const __half2* b) {
    __half2 m0 = __hmin2(__hmax2(a[0], b[7]), __hmax2(a[1], b[6]));
    __half2 m1 = __hmin2(__hmax2(a[2], b[5]), __hmax2(a[3], b[4]));
    __half2 m2 = __hmin2(__hmax2(a[4], b[3]), __hmax2(a[5], b[2]));
    __half2 m3 = __hmin2(__hmax2(a[6], b[1]), __hmax2(a[7], b[0]));
    return __hmin2(__hmin2(m0, m1), __hmin2(m2, m3));
}

// OS kernel: one block per v-row pair; 512 threads, thread t owns positions p=2t, 2t+1.
// Input pre-scaled by alpha/16 at load (min/max commute with positive scale; /16 is the CA divisor).
__global__ void __launch_bounds__(512, 2) os3_kernel(const float* __restrict__ data, float ae) {
    extern __shared__ unsigned char sm[];
    __half2* row2 = (__half2*)sm;                         // 1040 * 4 B
    __half2* Ls   = (__half2*)(sm + 4160);                // 8 * CS * 4 B
    __half2* Mm   = (__half2*)(sm + 4160 + 8 * CS * 4);

    const int t = threadIdx.x;
    const float2* srcA = (const float2*)(data + (size_t)(2 * blockIdx.x) * NR);
    const float2* srcB = (const float2*)(data + (size_t)(2 * blockIdx.x + 1) * NR);

    {   // load + scale + pack
        float2 fa = srcA[t], fb = srcB[t];
        __half2 h0 = __floats2half2_rn(fa.x * ae, fb.x * ae);
        __half2 h1 = __floats2half2_rn(fa.y * ae, fb.y * ae);
        row2[2 * t]     = h0;
        row2[2 * t + 1] = h1;
        if (t < 8) {  // wrap extension
            row2[1024 + 2 * t]     = h0;
            row2[1024 + 2 * t + 1] = h1;
        }
    }
    __syncthreads();

    // Phase A: build L(2t), L(2t+1) in registers; publish to smem.
    __half2 r[10];
    {
        const uint2* rp = (const uint2*)(row2 + 2 * t);
#pragma unroll
        for (int k = 0; k < 5; k++) {
            uint2 q = rp[k];
            r[2 * k]     = *(__half2*)&q.x;
            r[2 * k + 1] = *(__half2*)&q.y;
        }
    }
    __half2 La[8], Lb[8];
#pragma unroll
    for (int i = 0; i < 8; i++) { La[i] = r[i]; Lb[i] = r[i + 1]; }
    sort8h(La);
    sort8h(Lb);
#pragma unroll
    for (int c = 0; c < 8; c++) {
        uint2 v; v.x = *(unsigned*)&La[c]; v.y = *(unsigned*)&Lb[c];
        *(uint2*)&Ls[c * CS + 2 * t] = v;
        if (t < 16) *(uint2*)&Ls[c * CS + 2 * t + 1024] = v;
    }
    __syncthreads();

    // Phase B: M(p) = merge(L(p) [regs], L(p+8) [smem]).
    __half2 xb[8], yb[8];
#pragma unroll
    for (int c = 0; c < 8; c++) {
        uint2 q = *(const uint2*)&Ls[c * CS + 2 * t + 8];
        xb[c] = *(__half2*)&q.x;
        yb[c] = *(__half2*)&q.y;
    }
    __half2 M0[8], M1[8];
    merge_top8(La, xb, M0);
    merge_top8(Lb, yb, M1);
#pragma unroll
    for (int c = 0; c < 8; c++) {
        uint2 v; v.x = *(unsigned*)&M0[c]; v.y = *(unsigned*)&M1[c];
        *(uint2*)&Mm[c * CS + 2 * t] = v;
        if (t < 16) *(uint2*)&Mm[c * CS + 2 * t + 1024] = v;
    }
    __syncthreads();

    // Phase C: out r = p+20 uses M(p) [regs] and M(p+25) [smem].
    __half2 n0[8], n1[8];
#pragma unroll
    for (int c = 0; c < 8; c++) {
        n0[c] = Mm[c * CS + 2 * t + 25];
        n1[c] = Mm[c * CS + 2 * t + 26];
    }
    __half2 os0 = kth8(M0, n0);
    __half2 os1 = kth8(M1, n1);

    __half2* g2 = g_os2 + (size_t)blockIdx.x * NR;
    const int rr = (2 * t + 20) & RMASK;   // even; rr+1 adjacent
    uint2 o; o.x = *(unsigned*)&os0; o.y = *(unsigned*)&os1;
    *(uint2*)&g2[rr] = o;
}

// CA kernel: out(v) = box21(v) - box5(v) along v (circular mod 256); /16 and alpha pre-folded.
// Block = (batch, 16-wide r chunk): grid 1024, 256 threads.
__global__ void __launch_bounds__(256) ca_kernel(float* __restrict__ out) {
    __shared__ float tile[NV][17];     // 17-pad: conflict-free for 2x16 warp access
    const int b  = blockIdx.x >> 6;
    const int r0 = (blockIdx.x & 63) * 16;
    const int t  = threadIdx.x;

    const __half2* src = g_os2 + (size_t)b * (NV / 2) * NR + r0;
#pragma unroll
    for (int i = 0; i < 8; i++) {
        int idx = t + 256 * i;             // 0..2047
        int vp = idx >> 4, rl = idx & 15;
        __half2 v2 = src[(size_t)vp * NR + rl];
        tile[2 * vp][rl]     = __low2float(v2);
        tile[2 * vp + 1][rl] = __high2float(v2);
    }
    __syncthreads();

    const int rl = t & 15;
    const int v0 = (t >> 4) * 16;          // 16 segments of 16 v's

    float box21 = 0.0f, box5 = 0.0f;
#pragma unroll
    for (int d = -10; d <= 10; d++) {
        float x = tile[(v0 + d) & VMASK][rl];
        box21 += x;
        if (d >= -2 && d <= 2) box5 += x;
    }

    float* dst = out + (size_t)b * NV * NR + r0 + rl;
#pragma unroll
    for (int vi = 0; vi < 16; vi++) {
        const int v = v0 + vi;
        dst[(size_t)v * NR] = box21 - box5;
        box21 += tile[(v + 11) & VMASK][rl] - tile[(v - 10) & VMASK][rl];
        box5  += tile[(v + 3)  & VMASK][rl] - tile[(v - 2)  & VMASK][rl];
    }
}

// ---------------- host: replicate the reference's alpha solve ----------------

static double cfar_log_factorial(double n) {
    n += 1.0;
    if (n < 9.0) {
        double f = 1.0;
        int m = (int)(n + 0.5);
        for (int i = 2; i <= m; i++) f *= (double)i;
        return log(f);
    }
    return 0.5 * (log(2.0 * 3.14159265358979323846) - log(n))
         + n * (log(n + 1.0 / (12.0 * n - 1.0 / (10.0 * n))) - 1.0);
}

static double cfar_fun(int k, int n, double t, double pfa) {
    double s = 0.0;
    for (int j = n; j > n - k; j--) s += log((double)j + t);
    return cfar_log_factorial((double)n) - cfar_log_factorial((double)(n - k)) - s - log(pfa);
}

extern "C" void kernel_launch(void* const* d_in, const int* in_sizes, int n_in,
                              void* d_out, int out_size) {
    (void)in_sizes; (void)n_in; (void)out_size;
    const float* data = (const float*)d_in[0];
    float* out = (float*)d_out;

    double lo = 1.0, hi = 1.0e6;
    for (int it = 0; it < 200; it++) {
        double mid = 0.5 * (lo + hi);
        if (cfar_fun(24, 32, mid, 1.0e-5) > 0.0) lo = mid; else hi = mid;
    }
    float alpha_eff = (float)(sqrt(0.5 * (lo + hi)) / 16.0);   // alpha/16, CA divisor folded in

    const int OS_SMEM = 4160 + 2 * 8 * CS * 4;   // 71744 B
    cudaFuncSetAttribute(os3_kernel, cudaFuncAttributeMaxDynamicSharedMemorySize, OS_SMEM);

    os3_kernel<<<NB * NV / 2, 512, OS_SMEM>>>(data, alpha_eff);
    ca_kernel<<<NB * 64, 256>>>(out);
}